// round 11
// baseline (speedup 1.0000x reference)
#include <cuda_runtime.h>
#include <cuda_bf16.h>
#include <cstdint>

#define NUM_GRIDS 8

__device__ __forceinline__ float tanh_approx(float x) {
    float y;
    asm("tanh.approx.f32 %0, %1;" : "=f"(y) : "f"(x));
    return y;
}

__device__ __forceinline__ float bump(float xi, float g) {
    const float th = tanh_approx(xi - g);
    return 1.0f - th * th;
}

__device__ __forceinline__ void stg256(float* dst,
                                       float r0, float r1, float r2, float r3,
                                       float r4, float r5, float r6, float r7) {
    asm volatile(
        "st.global.cs.v8.f32 [%0], {%1,%2,%3,%4,%5,%6,%7,%8};"
        :: "l"(dst),
           "f"(r0), "f"(r1), "f"(r2), "f"(r3),
           "f"(r4), "f"(r5), "f"(r6), "f"(r7)
        : "memory");
}

// Persistent grid-stride kernel at FULL occupancy: 1184 CTAs = 8/SM on
// 148 SMs = 64 warps/SM (hardware max for 256-thread blocks).
// __launch_bounds__(256, 8) pins ptxas to <=32 regs so 8 CTAs/SM fit.
// Per iteration: 1x LDG.64 (warp = 256 B contiguous), 16 outputs via
// 2x STG.256 (warp = 2 KB contiguous). Unroll-2 hoists the next
// iteration's independent load above this iteration's stores.
__global__ __launch_bounds__(256, 8)
void rswaf_kernel(const float2* __restrict__ x,
                  const float4* __restrict__ grid,   // [8] floats = 2 float4
                  const float*  __restrict__ inv_den,
                  float*        __restrict__ out,
                  int n2) {
    const float inv = __ldg(inv_den);

    // pre-scale grid by inv: (x-g)*inv = x*inv - g*inv
    const float4 gA = __ldg(grid + 0);
    const float4 gB = __ldg(grid + 1);
    const float g0 = gA.x * inv, g1 = gA.y * inv, g2 = gA.z * inv, g3 = gA.w * inv;
    const float g4 = gB.x * inv, g5 = gB.y * inv, g6 = gB.z * inv, g7 = gB.w * inv;

    const int stride = gridDim.x * blockDim.x;

#pragma unroll 2
    for (int i = blockIdx.x * blockDim.x + threadIdx.x; i < n2; i += stride) {
        const float2 xv = __ldcs(x + i);
        const float xa = xv.x * inv;
        const float xb = xv.y * inv;

        float* dst = out + (long long)i * (2 * NUM_GRIDS);

        stg256(dst,
               bump(xa, g0), bump(xa, g1), bump(xa, g2), bump(xa, g3),
               bump(xa, g4), bump(xa, g5), bump(xa, g6), bump(xa, g7));

        stg256(dst + NUM_GRIDS,
               bump(xb, g0), bump(xb, g1), bump(xb, g2), bump(xb, g3),
               bump(xb, g4), bump(xb, g5), bump(xb, g6), bump(xb, g7));
    }
}

extern "C" void kernel_launch(void* const* d_in, const int* in_sizes, int n_in,
                              void* d_out, int out_size) {
    const float* x       = (const float*)d_in[0];   // [16,64,128,128] fp32
    const float* grid    = (const float*)d_in[1];   // [8] fp32
    const float* inv_den = (const float*)d_in[2];   // scalar fp32
    float* out = (float*)d_out;                     // [...,8] fp32

    const int n  = in_sizes[0];        // 16,777,216 (even)
    const int n2 = n >> 1;             // 8,388,608 float2s

    const int threads = 256;
    const int blocks  = 1184;          // 148 SMs x 8 CTAs = 64 warps/SM (max)

    rswaf_kernel<<<blocks, threads>>>(
        (const float2*)x, (const float4*)grid, inv_den, out, n2);
}

// round 12
// speedup vs baseline: 1.0804x; 1.0804x over previous
#include <cuda_runtime.h>
#include <cuda_bf16.h>
#include <cstdint>

#define NUM_GRIDS 8
#define THREADS 256
#define TILE_FLOATS 4096            // 16 KB output tile per CTA
#define TILE_F4     (TILE_FLOATS/4) // 1024 float4
#define TILE_ELEMS  (TILE_FLOATS/NUM_GRIDS) // 512 x-elements per tile

__device__ __forceinline__ float tanh_approx(float x) {
    float y;
    asm("tanh.approx.f32 %0, %1;" : "=f"(y) : "f"(x));
    return y;
}

__device__ __forceinline__ float bump(float xi, float g) {
    const float th = tanh_approx(xi - g);
    return 1.0f - th * th;
}

// Each CTA produces one 16 KB output tile in SMEM (in exact global order),
// then drains it with a single TMA bulk store (cp.async.bulk), bypassing
// the per-thread L1 store-wavefront path entirely.
//
// Thread t computes 4 output float4s: tile-local float4 index f4 = j*256 + t
// (j = 0..3). Each float4 is one half (4 grids) of one element's 8 outputs:
//   element-in-tile = f4 >> 1, grid half = (f4 & 1) * 4.
// STS: address = f4 * 16 B -> consecutive lanes write consecutive 16 B,
// bank-conflict-free. LDG: for fixed j, warp reads 16 consecutive elements
// (lane pairs share one) = 64 B coalesced; 4 independent loads per thread.
__global__ __launch_bounds__(THREADS)
void rswaf_kernel(const float*  __restrict__ x,
                  const float4* __restrict__ grid,   // [8] floats = 2 float4
                  const float*  __restrict__ inv_den,
                  float*        __restrict__ out) {
    __shared__ __align__(128) float tile[TILE_FLOATS];

    const int t = threadIdx.x;
    const float inv = __ldg(inv_den);

    // pre-scale grid by inv: (x-g)*inv = x*inv - g*inv
    const float4 gA = __ldg(grid + 0);
    const float4 gB = __ldg(grid + 1);
    const float gs[NUM_GRIDS] = {gA.x * inv, gA.y * inv, gA.z * inv, gA.w * inv,
                                 gB.x * inv, gB.y * inv, gB.z * inv, gB.w * inv};

    const int elem_base = blockIdx.x * TILE_ELEMS;

    // 4 independent x loads up front (MLP = 4)
    float xi[4];
#pragma unroll
    for (int j = 0; j < 4; j++) {
        const int f4 = j * THREADS + t;
        xi[j] = __ldcs(x + elem_base + (f4 >> 1)) * inv;
    }

#pragma unroll
    for (int j = 0; j < 4; j++) {
        const int f4 = j * THREADS + t;
        const int h  = (f4 & 1) << 2;        // grids 0..3 or 4..7
        float4 o;
        o.x = bump(xi[j], gs[h + 0]);
        o.y = bump(xi[j], gs[h + 1]);
        o.z = bump(xi[j], gs[h + 2]);
        o.w = bump(xi[j], gs[h + 3]);
        reinterpret_cast<float4*>(tile)[f4] = o;   // STS.128, conflict-free
    }

    __syncthreads();

    if (t == 0) {
        // order generic-proxy STS before async-proxy TMA read
        asm volatile("fence.proxy.async.shared::cta;" ::: "memory");

        uint32_t smem_addr;
        asm("{ .reg .u64 a; cvta.to.shared.u64 a, %1; cvt.u32.u64 %0, a; }"
            : "=r"(smem_addr) : "l"(tile));

        float* dst = out + (long long)blockIdx.x * TILE_FLOATS;
        asm volatile(
            "cp.async.bulk.global.shared::cta.bulk_group [%0], [%1], %2;"
            :: "l"(dst), "r"(smem_addr), "n"(TILE_FLOATS * 4)
            : "memory");
        asm volatile("cp.async.bulk.commit_group;" ::: "memory");
        asm volatile("cp.async.bulk.wait_group 0;" ::: "memory");
    }
}

extern "C" void kernel_launch(void* const* d_in, const int* in_sizes, int n_in,
                              void* d_out, int out_size) {
    const float* x       = (const float*)d_in[0];   // [16,64,128,128] fp32
    const float* grid    = (const float*)d_in[1];   // [8] fp32
    const float* inv_den = (const float*)d_in[2];   // scalar fp32
    float* out = (float*)d_out;                     // [...,8] fp32

    const int tiles = out_size / TILE_FLOATS;       // 134217728/4096 = 32768

    rswaf_kernel<<<tiles, THREADS>>>(
        x, (const float4*)grid, inv_den, out);
}

// round 13
// speedup vs baseline: 1.1479x; 1.0626x over previous
#include <cuda_runtime.h>
#include <cuda_bf16.h>
#include <cstdint>

#define NUM_GRIDS 8

__device__ __forceinline__ float tanh_approx(float x) {
    float y;
    asm("tanh.approx.f32 %0, %1;" : "=f"(y) : "f"(x));
    return y;
}

__device__ __forceinline__ float bump(float xi, float g) {
    const float th = tanh_approx(xi - g);
    return 1.0f - th * th;
}

// Default write-back policy (no .cs): let L2 accumulate full dirty lines and
// drain in large batches instead of evict-first's eager small writebacks.
__device__ __forceinline__ void stg256_wb(float* dst,
                                          float r0, float r1, float r2, float r3,
                                          float r4, float r5, float r6, float r7) {
    asm volatile(
        "st.global.v8.f32 [%0], {%1,%2,%3,%4,%5,%6,%7,%8};"
        :: "l"(dst),
           "f"(r0), "f"(r1), "f"(r2), "f"(r3),
           "f"(r4), "f"(r5), "f"(r6), "f"(r7)
        : "memory");
}

// Best-measured shape (R9): flat grid, 2 elements/thread.
// 1x LDG.64 in (warp = 256 B contiguous), 16 outputs via 2x STG.256
// (warp = 2 KB contiguous). All results in named scalars, regs ~27.
__global__ __launch_bounds__(256)
void rswaf_kernel(const float2* __restrict__ x,
                  const float4* __restrict__ grid,   // [8] floats = 2 float4
                  const float*  __restrict__ inv_den,
                  float*        __restrict__ out,
                  int n2) {
    const int i = blockIdx.x * blockDim.x + threadIdx.x;
    if (i >= n2) return;

    const float inv = __ldg(inv_den);

    // pre-scale grid by inv: (x-g)*inv = x*inv - g*inv
    const float4 gA = __ldg(grid + 0);
    const float4 gB = __ldg(grid + 1);
    const float g0 = gA.x * inv, g1 = gA.y * inv, g2 = gA.z * inv, g3 = gA.w * inv;
    const float g4 = gB.x * inv, g5 = gB.y * inv, g6 = gB.z * inv, g7 = gB.w * inv;

    const float2 xv = __ldcs(x + i);     // read stream: evict-first is right
    const float xa = xv.x * inv;
    const float xb = xv.y * inv;

    float* dst = out + (long long)i * (2 * NUM_GRIDS);

    stg256_wb(dst,
              bump(xa, g0), bump(xa, g1), bump(xa, g2), bump(xa, g3),
              bump(xa, g4), bump(xa, g5), bump(xa, g6), bump(xa, g7));

    stg256_wb(dst + NUM_GRIDS,
              bump(xb, g0), bump(xb, g1), bump(xb, g2), bump(xb, g3),
              bump(xb, g4), bump(xb, g5), bump(xb, g6), bump(xb, g7));
}

extern "C" void kernel_launch(void* const* d_in, const int* in_sizes, int n_in,
                              void* d_out, int out_size) {
    const float* x       = (const float*)d_in[0];   // [16,64,128,128] fp32
    const float* grid    = (const float*)d_in[1];   // [8] fp32
    const float* inv_den = (const float*)d_in[2];   // scalar fp32
    float* out = (float*)d_out;                     // [...,8] fp32

    const int n  = in_sizes[0];        // 16,777,216 (even)
    const int n2 = n >> 1;             // 8,388,608 float2s

    const int threads = 256;
    const int blocks  = (n2 + threads - 1) / threads;   // 32768

    rswaf_kernel<<<blocks, threads>>>(
        (const float2*)x, (const float4*)grid, inv_den, out, n2);
}

// round 14
// speedup vs baseline: 1.1535x; 1.0049x over previous
#include <cuda_runtime.h>
#include <cuda_bf16.h>
#include <cstdint>

#define NUM_GRIDS 8

__device__ __forceinline__ float tanh_approx(float x) {
    float y;
    asm("tanh.approx.f32 %0, %1;" : "=f"(y) : "f"(x));
    return y;
}

__device__ __forceinline__ float bump(float xi, float g) {
    const float th = tanh_approx(xi - g);
    return 1.0f - th * th;
}

// Default write-back policy (no .cs): let L2 accumulate full dirty lines and
// drain in large batches instead of evict-first's eager small writebacks.
__device__ __forceinline__ void stg256_wb(float* dst,
                                          float r0, float r1, float r2, float r3,
                                          float r4, float r5, float r6, float r7) {
    asm volatile(
        "st.global.v8.f32 [%0], {%1,%2,%3,%4,%5,%6,%7,%8};"
        :: "l"(dst),
           "f"(r0), "f"(r1), "f"(r2), "f"(r3),
           "f"(r4), "f"(r5), "f"(r6), "f"(r7)
        : "memory");
}

// Best-measured shape (R9): flat grid, 2 elements/thread.
// 1x LDG.64 in (warp = 256 B contiguous), 16 outputs via 2x STG.256
// (warp = 2 KB contiguous). All results in named scalars, regs ~27.
__global__ __launch_bounds__(256)
void rswaf_kernel(const float2* __restrict__ x,
                  const float4* __restrict__ grid,   // [8] floats = 2 float4
                  const float*  __restrict__ inv_den,
                  float*        __restrict__ out,
                  int n2) {
    const int i = blockIdx.x * blockDim.x + threadIdx.x;
    if (i >= n2) return;

    const float inv = __ldg(inv_den);

    // pre-scale grid by inv: (x-g)*inv = x*inv - g*inv
    const float4 gA = __ldg(grid + 0);
    const float4 gB = __ldg(grid + 1);
    const float g0 = gA.x * inv, g1 = gA.y * inv, g2 = gA.z * inv, g3 = gA.w * inv;
    const float g4 = gB.x * inv, g5 = gB.y * inv, g6 = gB.z * inv, g7 = gB.w * inv;

    const float2 xv = __ldcs(x + i);     // read stream: evict-first is right
    const float xa = xv.x * inv;
    const float xb = xv.y * inv;

    float* dst = out + (long long)i * (2 * NUM_GRIDS);

    stg256_wb(dst,
              bump(xa, g0), bump(xa, g1), bump(xa, g2), bump(xa, g3),
              bump(xa, g4), bump(xa, g5), bump(xa, g6), bump(xa, g7));

    stg256_wb(dst + NUM_GRIDS,
              bump(xb, g0), bump(xb, g1), bump(xb, g2), bump(xb, g3),
              bump(xb, g4), bump(xb, g5), bump(xb, g6), bump(xb, g7));
}

extern "C" void kernel_launch(void* const* d_in, const int* in_sizes, int n_in,
                              void* d_out, int out_size) {
    const float* x       = (const float*)d_in[0];   // [16,64,128,128] fp32
    const float* grid    = (const float*)d_in[1];   // [8] fp32
    const float* inv_den = (const float*)d_in[2];   // scalar fp32
    float* out = (float*)d_out;                     // [...,8] fp32

    const int n  = in_sizes[0];        // 16,777,216 (even)
    const int n2 = n >> 1;             // 8,388,608 float2s

    const int threads = 256;
    const int blocks  = (n2 + threads - 1) / threads;   // 32768

    rswaf_kernel<<<blocks, threads>>>(
        (const float2*)x, (const float4*)grid, inv_den, out, n2);
}